// round 13
// baseline (speedup 1.0000x reference)
#include <cuda_runtime.h>
#include <cstdint>
#include <math.h>

#define KNBR  32
#define D     128
#define T     512
#define B_TOT 32768
#define NQUAD (B_TOT / 4)   // 4 rows (2 pairs) per macro-iteration

// smem layout (float offsets)
#define OFF_HN    0        // 2 * 16384 double-buffered (4 rows x 4096)
#define OFF_HE    32768    // 2 * 512
#define OFF_MSK   33792    // 2 * 128 ints
#define OFF_VS    34048    // 256 (v_ego | v_nbr)
#define OFF_EGO2  34304    // 512: ego2[pair*256 + 2*d + r]
#define OFF_AGG2  34816    // 512
#define OFF_REDD  35328    // 2048: 16 warps x 128
#define OFF_REDE  37376    // 2 * 4096: DOUBLE-BUFFERED proj results (2048 u64 each)
#define OFF_LOG   45568    // 128
#define OFF_ATT   45696    // 128
#define SMEM_FLOATS 45824
#define SMEM_BYTES (SMEM_FLOATS * 4)

__device__ float g_v[2 * D];   // [0:128) v_ego = W_msg^T a_ego, [128:256) v_nbr

// ---------------- prologue: v = W_msg^T @ a ----------------
__global__ void prep_kernel(const float* __restrict__ Wmsg,
                            const float* __restrict__ Wattn) {
    int d = threadIdx.x;   // 128 threads
    float ve = 0.f, vn = 0.f;
    #pragma unroll 8
    for (int e = 0; e < D; e++) {
        float w = Wmsg[e * D + d];
        ve = fmaf(Wattn[e], w, ve);
        vn = fmaf(Wattn[D + e], w, vn);
    }
    g_v[d] = ve;
    g_v[D + d] = vn;
}

// ---------------- cp.async helpers ----------------
__device__ __forceinline__ void cp16(uint32_t dst, const void* src) {
    asm volatile("cp.async.cg.shared.global [%0], [%1], 16;" :: "r"(dst), "l"(src));
}
__device__ __forceinline__ void cp_commit() { asm volatile("cp.async.commit_group;"); }
__device__ __forceinline__ void cp_wait1()  { asm volatile("cp.async.wait_group 1;" ::: "memory"); }
__device__ __forceinline__ void cp_waitall(){ asm volatile("cp.async.wait_all;" ::: "memory"); }

__device__ __forceinline__ void prefetch_quad(int q, int buf, int tid, uint32_t smem_u32,
                                              const float* __restrict__ h_nei,
                                              const float* __restrict__ h_ego,
                                              const int*   __restrict__ nbr_mask) {
    const float* src = h_nei + (size_t)q * 16384;
    uint32_t hdst = smem_u32 + (uint32_t)(OFF_HN + buf * 16384) * 4u;
    #pragma unroll
    for (int i = 0; i < 8; i++) {                        // 4096 float4
        int idx = tid + i * T;
        cp16(hdst + (uint32_t)idx * 16u, src + idx * 4);
    }
    if (tid < 128)
        cp16(smem_u32 + (uint32_t)(OFF_HE + buf * 512 + tid * 4) * 4u,
             h_ego + (size_t)q * 512 + tid * 4);
    if (tid < 32)
        cp16(smem_u32 + (uint32_t)(OFF_MSK + buf * 128 + tid * 4) * 4u,
             nbr_mask + (size_t)q * 128 + tid * 4);
}

// ---------------- FFMA2 projection: 2 outputs (e, e+64) x 32 inputs, both pairs ----------------
__device__ __forceinline__ void proj2x32(const unsigned long long* __restrict__ xq,
                                         const float* __restrict__ wreg,
                                         int c0,
                                         unsigned long long* __restrict__ rE,
                                         int slot_e0, int slot_e1) {
    unsigned long long a00 = 0ull, a01 = 0ull, a10 = 0ull, a11 = 0ull;
    #pragma unroll
    for (int dd = 0; dd < 32; dd += 2) {
        ulonglong2 x0 = *(const ulonglong2*)&xq[c0 + dd];         // pair0: d, d+1
        ulonglong2 x1 = *(const ulonglong2*)&xq[128 + c0 + dd];   // pair1: d, d+1
        unsigned long long w0, w1, w0b, w1b;
        unsigned int wa  = __float_as_uint(wreg[dd]);
        unsigned int wb  = __float_as_uint(wreg[32 + dd]);
        unsigned int wa1 = __float_as_uint(wreg[dd + 1]);
        unsigned int wb1 = __float_as_uint(wreg[32 + dd + 1]);
        asm("mov.b64 %0, {%1,%1};" : "=l"(w0)  : "r"(wa));
        asm("mov.b64 %0, {%1,%1};" : "=l"(w1)  : "r"(wb));
        asm("mov.b64 %0, {%1,%1};" : "=l"(w0b) : "r"(wa1));
        asm("mov.b64 %0, {%1,%1};" : "=l"(w1b) : "r"(wb1));
        asm("fma.rn.f32x2 %0, %1, %2, %3;" : "=l"(a00) : "l"(w0),  "l"(x0.x), "l"(a00));
        asm("fma.rn.f32x2 %0, %1, %2, %3;" : "=l"(a01) : "l"(w1),  "l"(x0.x), "l"(a01));
        asm("fma.rn.f32x2 %0, %1, %2, %3;" : "=l"(a10) : "l"(w0),  "l"(x1.x), "l"(a10));
        asm("fma.rn.f32x2 %0, %1, %2, %3;" : "=l"(a11) : "l"(w1),  "l"(x1.x), "l"(a11));
        asm("fma.rn.f32x2 %0, %1, %2, %3;" : "=l"(a00) : "l"(w0b), "l"(x0.y), "l"(a00));
        asm("fma.rn.f32x2 %0, %1, %2, %3;" : "=l"(a01) : "l"(w1b), "l"(x0.y), "l"(a01));
        asm("fma.rn.f32x2 %0, %1, %2, %3;" : "=l"(a10) : "l"(w0b), "l"(x1.y), "l"(a10));
        asm("fma.rn.f32x2 %0, %1, %2, %3;" : "=l"(a11) : "l"(w1b), "l"(x1.y), "l"(a11));
    }
    rE[slot_e0]        = a00;
    rE[slot_e1]        = a01;
    rE[1024 + slot_e0] = a10;
    rE[1024 + slot_e1] = a11;
}

// ---------------- deferred combine + tanh + store (threads 128..383) ----------------
__device__ __forceinline__ void combine_store(int tid, int qc, const float* __restrict__ redEbuf,
                                              float bb, float* __restrict__ out) {
    int ct = tid - 128, pr = ct >> 7, dd = ct & 127;
    const float2* r = (const float2*)redEbuf + pr * 1024;
    float2 r0 = r[0 * 128 + dd];
    float2 r1 = r[1 * 128 + dd];
    float2 r2 = r[2 * 128 + dd];
    float2 r3 = r[3 * 128 + dd];
    float2 r4 = r[4 * 128 + dd];
    float2 r5 = r[5 * 128 + dd];
    float2 r6 = r[6 * 128 + dd];
    float2 r7 = r[7 * 128 + dd];
    float sx = ((r0.x + r1.x) + (r2.x + r3.x)) + ((r4.x + r5.x) + (r6.x + r7.x));
    float sy = ((r0.y + r1.y) + (r2.y + r3.y)) + ((r4.y + r5.y) + (r6.y + r7.y));
    float o0 = tanhf(sx + bb);
    float o1 = tanhf(sy + bb);
    size_t row = ((size_t)4 * qc + 2 * pr) * D;
    out[row + dd]     = o0;
    out[row + D + dd] = o1;
}

// ---------------- main fused kernel ----------------
__global__ void __launch_bounds__(T, 1)
gat_kernel(const float* __restrict__ h_ego, const float* __restrict__ h_nei,
           const int*   __restrict__ nbr_mask,
           const float* __restrict__ Wmsg, const float* __restrict__ Wself,
           const float* __restrict__ bself, float* __restrict__ out) {
    extern __shared__ float sm[];
    float* hn    = sm + OFF_HN;
    float* he    = sm + OFF_HE;
    int*   msk   = (int*)(sm + OFF_MSK);
    float* vs    = sm + OFF_VS;
    float* ego2  = sm + OFF_EGO2;
    float* agg2  = sm + OFF_AGG2;
    float* redD  = sm + OFF_REDD;
    float* redE  = sm + OFF_REDE;
    float* logit = sm + OFF_LOG;
    float* attn  = sm + OFF_ATT;

    const int tid  = threadIdx.x;
    const int lane = tid & 31;
    const int warp = tid >> 5;
    const int rr   = warp >> 2;           // row within quad (0..3)
    const int kq   = (warp & 3) * 8;      // 8 k's per warp

    // projection tile: m = matrix (0: Wmsg / agg2, 1: Wself / ego2)
    const int m    = tid >> 8;            // 0..1
    const int h    = (tid >> 6) & 3;      // input quarter
    const int e6   = tid & 63;            // output pair base (outputs e6 and e6+64)
    const int c0   = h * 32;              // first input dim
    const int slot_e0 = h * 256 + m * 128 + e6;
    const int slot_e1 = slot_e0 + 64;

    // W slices in registers: rows e6 and e6+64, cols [c0, c0+32)
    const float* Wsrc = (m == 0) ? Wmsg : Wself;
    float wreg[64];
    #pragma unroll
    for (int j = 0; j < 32; j += 4) {
        float4 t4 = *(const float4*)&Wsrc[e6 * D + c0 + j];
        wreg[j] = t4.x; wreg[j + 1] = t4.y; wreg[j + 2] = t4.z; wreg[j + 3] = t4.w;
        float4 t5 = *(const float4*)&Wsrc[(e6 + 64) * D + c0 + j];
        wreg[32 + j] = t5.x; wreg[33 + j] = t5.y; wreg[34 + j] = t5.z; wreg[35 + j] = t5.w;
    }
    if (tid < 2 * D) vs[tid] = g_v[tid];
    float bb = __ldg(bself + (tid & 127));
    __syncthreads();

    const uint32_t smem_u32 = (uint32_t)__cvta_generic_to_shared(sm);
    const float NEG_INF = __int_as_float(0xff800000);
    const int G = gridDim.x;

    int q = blockIdx.x;
    int s = 0;
    int it = 0;
    int lastq = -1;
    if (q < NQUAD) prefetch_quad(q, 0, tid, smem_u32, h_nei, h_ego, nbr_mask);
    cp_commit();

    for (; q < NQUAD; q += G, s ^= 1, it++) {
        int qn = q + G;
        if (qn < NQUAD) prefetch_quad(qn, s ^ 1, tid, smem_u32, h_nei, h_ego, nbr_mask);
        cp_commit();
        cp_wait1();
        __syncthreads();   // B0: buffer s ready; prev proj results visible

        const float* hnb  = &hn[s * 16384];
        const float* heb  = &he[s * 512];
        const int*   mskb = &msk[s * 128];
        const float* hb   = &hnb[rr * 4096 + kq * 128];

        // ---- stage fragments ONCE; compute raw neighbor dots ----
        float4 f0 = *(const float4*)&hb[0 * 128 + lane * 4];
        float4 f1 = *(const float4*)&hb[1 * 128 + lane * 4];
        float4 f2 = *(const float4*)&hb[2 * 128 + lane * 4];
        float4 f3 = *(const float4*)&hb[3 * 128 + lane * 4];
        float4 f4 = *(const float4*)&hb[4 * 128 + lane * 4];
        float4 f5 = *(const float4*)&hb[5 * 128 + lane * 4];
        float4 f6 = *(const float4*)&hb[6 * 128 + lane * 4];
        float4 f7 = *(const float4*)&hb[7 * 128 + lane * 4];
        {
            float4 vN = *(const float4*)&vs[D + lane * 4];
            float a0 = f0.x * vN.x + f0.y * vN.y + f0.z * vN.z + f0.w * vN.w;
            float a1 = f1.x * vN.x + f1.y * vN.y + f1.z * vN.z + f1.w * vN.w;
            float a2 = f2.x * vN.x + f2.y * vN.y + f2.z * vN.z + f2.w * vN.w;
            float a3 = f3.x * vN.x + f3.y * vN.y + f3.z * vN.z + f3.w * vN.w;
            float a4 = f4.x * vN.x + f4.y * vN.y + f4.z * vN.z + f4.w * vN.w;
            float a5 = f5.x * vN.x + f5.y * vN.y + f5.z * vN.z + f5.w * vN.w;
            float a6 = f6.x * vN.x + f6.y * vN.y + f6.z * vN.z + f6.w * vN.w;
            float a7 = f7.x * vN.x + f7.y * vN.y + f7.z * vN.z + f7.w * vN.w;

            // pair-combining butterfly: 8 values -> 1 per lane-class
            const unsigned FULL = 0xffffffffu;
            bool h16 = (lane & 16) != 0;
            float s0, o0;
            s0 = h16 ? a1 : a0; o0 = h16 ? a0 : a1;
            float b0 = s0 + __shfl_xor_sync(FULL, o0, 16);
            s0 = h16 ? a3 : a2; o0 = h16 ? a2 : a3;
            float b1 = s0 + __shfl_xor_sync(FULL, o0, 16);
            s0 = h16 ? a5 : a4; o0 = h16 ? a4 : a5;
            float b2 = s0 + __shfl_xor_sync(FULL, o0, 16);
            s0 = h16 ? a7 : a6; o0 = h16 ? a6 : a7;
            float b3 = s0 + __shfl_xor_sync(FULL, o0, 16);

            bool h8 = (lane & 8) != 0;
            s0 = h8 ? b1 : b0; o0 = h8 ? b0 : b1;
            float c0v = s0 + __shfl_xor_sync(FULL, o0, 8);
            s0 = h8 ? b3 : b2; o0 = h8 ? b2 : b3;
            float c1v = s0 + __shfl_xor_sync(FULL, o0, 8);

            bool h4 = (lane & 4) != 0;
            s0 = h4 ? c1v : c0v; o0 = h4 ? c0v : c1v;
            float dsum = s0 + __shfl_xor_sync(FULL, o0, 4);

            dsum += __shfl_xor_sync(FULL, dsum, 2);
            dsum += __shfl_xor_sync(FULL, dsum, 1);

            if ((lane & 3) == 0) {
                int kl = ((lane >> 4) & 1) | (((lane >> 3) & 1) << 1) | (((lane >> 2) & 1) << 2);
                logit[rr * KNBR + kq + kl] = dsum;
            }
        }
        // pack ego batch-major (threads 256..511 handle 2 each) — needed before A1
        if (tid >= 256) {
            int t = tid - 256;
            #pragma unroll
            for (int i = 0; i < 2; i++) {
                int idx = t + i * 256;          // 0..511
                int r = idx >> 7, dd = idx & 127;
                ego2[(r >> 1) * 256 + 2 * dd + (r & 1)] = heb[r * 128 + dd];
            }
        }
        __syncthreads();   // A1: logits + ego2 ready

        // ---- softmax (warps 0..3) || deferred combine of PREVIOUS quad (warps 4..11) ----
        if (warp < 4) {
            float4 vE = *(const float4*)&vs[lane * 4];
            float4 eg = *(const float4*)&heb[warp * 128 + lane * 4];
            float pe = eg.x * vE.x + eg.y * vE.y + eg.z * vE.z + eg.w * vE.w;
            #pragma unroll
            for (int o = 16; o > 0; o >>= 1) pe += __shfl_xor_sync(0xffffffffu, pe, o);
            float x = logit[warp * KNBR + lane] + pe;
            x = (x > 0.f) ? x : 0.2f * x;                          // leaky_relu
            x = (mskb[warp * KNBR + lane] > 0) ? x : NEG_INF;      // mask
            float mx = x;
            #pragma unroll
            for (int o = 16; o > 0; o >>= 1) mx = fmaxf(mx, __shfl_xor_sync(0xffffffffu, mx, o));
            float ee = (x == NEG_INF) ? 0.f : __expf(x - mx);
            float ss = ee;
            #pragma unroll
            for (int o = 16; o > 0; o >>= 1) ss += __shfl_xor_sync(0xffffffffu, ss, o);
            attn[warp * KNBR + lane] = (ss > 0.f) ? (ee / ss) : 0.f;
        } else if (it > 0 && tid < 384) {
            combine_store(tid, q - G, redE + (s ^ 1) * 4096, bb, out);
        }
        __syncthreads();   // A2: attn ready

        // ---- weighted partial aggregation from HELD registers ----
        {
            float4 atv0 = *(const float4*)&attn[rr * KNBR + kq];
            float4 atv1 = *(const float4*)&attn[rr * KNBR + kq + 4];
            float a0 = atv0.x, a1 = atv0.y, a2 = atv0.z, a3 = atv0.w;
            float a4 = atv1.x, a5 = atv1.y, a6 = atv1.z, a7 = atv1.w;
            float4 acc;
            acc.x = a0 * f0.x; acc.y = a0 * f0.y; acc.z = a0 * f0.z; acc.w = a0 * f0.w;
            acc.x = fmaf(a1, f1.x, acc.x); acc.y = fmaf(a1, f1.y, acc.y);
            acc.z = fmaf(a1, f1.z, acc.z); acc.w = fmaf(a1, f1.w, acc.w);
            acc.x = fmaf(a2, f2.x, acc.x); acc.y = fmaf(a2, f2.y, acc.y);
            acc.z = fmaf(a2, f2.z, acc.z); acc.w = fmaf(a2, f2.w, acc.w);
            acc.x = fmaf(a3, f3.x, acc.x); acc.y = fmaf(a3, f3.y, acc.y);
            acc.z = fmaf(a3, f3.z, acc.z); acc.w = fmaf(a3, f3.w, acc.w);
            acc.x = fmaf(a4, f4.x, acc.x); acc.y = fmaf(a4, f4.y, acc.y);
            acc.z = fmaf(a4, f4.z, acc.z); acc.w = fmaf(a4, f4.w, acc.w);
            acc.x = fmaf(a5, f5.x, acc.x); acc.y = fmaf(a5, f5.y, acc.y);
            acc.z = fmaf(a5, f5.z, acc.z); acc.w = fmaf(a5, f5.w, acc.w);
            acc.x = fmaf(a6, f6.x, acc.x); acc.y = fmaf(a6, f6.y, acc.y);
            acc.z = fmaf(a6, f6.z, acc.z); acc.w = fmaf(a6, f6.w, acc.w);
            acc.x = fmaf(a7, f7.x, acc.x); acc.y = fmaf(a7, f7.y, acc.y);
            acc.z = fmaf(a7, f7.z, acc.z); acc.w = fmaf(a7, f7.w, acc.w);
            ((float4*)redD)[warp * 32 + lane] = acc;
        }
        __syncthreads();   // A3

        // ---- reduce 4 partials per (row,dim) -> batch-packed agg2 ----
        {
            int r  = tid >> 7;        // 0..3 (row)
            int dd = tid & 127;
            const float* rb = &redD[(4 * r) * 128 + dd];
            agg2[(r >> 1) * 256 + 2 * dd + (r & 1)] =
                rb[0] + rb[128] + rb[256] + rb[384];
        }
        __syncthreads();   // A4

        // ---- BOTH projections concurrently: msg (threads 0..255) / ego (256..511) ----
        {
            const unsigned long long* xq = (m == 0)
                ? (const unsigned long long*)agg2
                : (const unsigned long long*)ego2;
            proj2x32(xq, wreg, c0,
                     (unsigned long long*)(redE + s * 4096), slot_e0, slot_e1);
        }
        lastq = q;
        // no A5: results consumed next iteration after B0 (or in epilogue)
    }
    cp_waitall();
    __syncthreads();   // final proj results visible
    if (lastq >= 0 && tid >= 128 && tid < 384)
        combine_store(tid, lastq, redE + (s ^ 1) * 4096, bb, out);
}

// ---------------- launch ----------------
extern "C" void kernel_launch(void* const* d_in, const int* in_sizes, int n_in,
                              void* d_out, int out_size) {
    const float* h_ego  = (const float*)d_in[0];
    const float* h_nei  = (const float*)d_in[1];
    const int*   nmask  = (const int*)  d_in[2];
    const float* Wmsg   = (const float*)d_in[3];
    const float* Wattn  = (const float*)d_in[4];
    const float* Wself  = (const float*)d_in[5];
    const float* bself  = (const float*)d_in[6];
    float* out = (float*)d_out;

    int sms = 0;
    cudaDeviceGetAttribute(&sms, cudaDevAttrMultiProcessorCount, 0);
    if (sms <= 0) sms = 148;

    cudaFuncSetAttribute(gat_kernel, cudaFuncAttributeMaxDynamicSharedMemorySize, SMEM_BYTES);

    prep_kernel<<<1, D>>>(Wmsg, Wattn);
    gat_kernel<<<sms, T, SMEM_BYTES>>>(h_ego, h_nei, nmask, Wmsg, Wself, bself, out);
}

// round 14
// speedup vs baseline: 1.0856x; 1.0856x over previous
#include <cuda_runtime.h>
#include <cstdint>
#include <math.h>

#define KNBR  32
#define D     128
#define T     512
#define B_TOT 32768
#define NQUAD (B_TOT / 4)   // 4 rows (2 pairs) per macro-iteration

// smem layout (float offsets)
#define OFF_HN    0        // 2 * 16384 double-buffered (4 rows x 4096)
#define OFF_HE    32768    // 2 * 512
#define OFF_MSK   33792    // 2 * 128 ints
#define OFF_VS    34048    // 256 (v_ego | v_nbr)
#define OFF_EGO2  34304    // 512: ego2[pair*256 + 2*d + r]
#define OFF_AGG2  34816    // 512
#define OFF_REDD  35328    // 2048: 16 warps x 128
#define OFF_REDE  37376    // 2 * 4096: DOUBLE-BUFFERED proj results (2048 u64 each)
#define OFF_LOG   45568    // 128
#define OFF_ATT   45696    // 128
#define SMEM_FLOATS 45824
#define SMEM_BYTES (SMEM_FLOATS * 4)

__device__ float g_v[2 * D];   // [0:128) v_ego = W_msg^T a_ego, [128:256) v_nbr

// ---------------- prologue: v = W_msg^T @ a ----------------
__global__ void prep_kernel(const float* __restrict__ Wmsg,
                            const float* __restrict__ Wattn) {
    int d = threadIdx.x;   // 128 threads
    float ve = 0.f, vn = 0.f;
    #pragma unroll 8
    for (int e = 0; e < D; e++) {
        float w = Wmsg[e * D + d];
        ve = fmaf(Wattn[e], w, ve);
        vn = fmaf(Wattn[D + e], w, vn);
    }
    g_v[d] = ve;
    g_v[D + d] = vn;
}

// ---------------- cp.async helpers ----------------
__device__ __forceinline__ void cp16(uint32_t dst, const void* src) {
    asm volatile("cp.async.cg.shared.global [%0], [%1], 16;" :: "r"(dst), "l"(src));
}
__device__ __forceinline__ void cp_commit() { asm volatile("cp.async.commit_group;"); }
__device__ __forceinline__ void cp_wait1()  { asm volatile("cp.async.wait_group 1;" ::: "memory"); }
__device__ __forceinline__ void cp_waitall(){ asm volatile("cp.async.wait_all;" ::: "memory"); }

__device__ __forceinline__ void prefetch_quad(int q, int buf, int tid, uint32_t smem_u32,
                                              const float* __restrict__ h_nei,
                                              const float* __restrict__ h_ego,
                                              const int*   __restrict__ nbr_mask) {
    const float* src = h_nei + (size_t)q * 16384;
    uint32_t hdst = smem_u32 + (uint32_t)(OFF_HN + buf * 16384) * 4u;
    #pragma unroll
    for (int i = 0; i < 8; i++) {                        // 4096 float4
        int idx = tid + i * T;
        cp16(hdst + (uint32_t)idx * 16u, src + idx * 4);
    }
    if (tid < 128)
        cp16(smem_u32 + (uint32_t)(OFF_HE + buf * 512 + tid * 4) * 4u,
             h_ego + (size_t)q * 512 + tid * 4);
    if (tid < 32)
        cp16(smem_u32 + (uint32_t)(OFF_MSK + buf * 128 + tid * 4) * 4u,
             nbr_mask + (size_t)q * 128 + tid * 4);
}

// ---------------- FFMA2 projection: 2 outputs (e, e+64) x 32 inputs, both pairs ----------------
__device__ __forceinline__ void proj2x32(const unsigned long long* __restrict__ xq,
                                         const float* __restrict__ wreg,
                                         int c0,
                                         unsigned long long* __restrict__ rE,
                                         int slot_e0, int slot_e1) {
    unsigned long long a00 = 0ull, a01 = 0ull, a10 = 0ull, a11 = 0ull;
    #pragma unroll
    for (int dd = 0; dd < 32; dd += 2) {
        ulonglong2 x0 = *(const ulonglong2*)&xq[c0 + dd];         // pair0: d, d+1
        ulonglong2 x1 = *(const ulonglong2*)&xq[128 + c0 + dd];   // pair1: d, d+1
        unsigned long long w0, w1, w0b, w1b;
        unsigned int wa  = __float_as_uint(wreg[dd]);
        unsigned int wb  = __float_as_uint(wreg[32 + dd]);
        unsigned int wa1 = __float_as_uint(wreg[dd + 1]);
        unsigned int wb1 = __float_as_uint(wreg[32 + dd + 1]);
        asm("mov.b64 %0, {%1,%1};" : "=l"(w0)  : "r"(wa));
        asm("mov.b64 %0, {%1,%1};" : "=l"(w1)  : "r"(wb));
        asm("mov.b64 %0, {%1,%1};" : "=l"(w0b) : "r"(wa1));
        asm("mov.b64 %0, {%1,%1};" : "=l"(w1b) : "r"(wb1));
        asm("fma.rn.f32x2 %0, %1, %2, %3;" : "=l"(a00) : "l"(w0),  "l"(x0.x), "l"(a00));
        asm("fma.rn.f32x2 %0, %1, %2, %3;" : "=l"(a01) : "l"(w1),  "l"(x0.x), "l"(a01));
        asm("fma.rn.f32x2 %0, %1, %2, %3;" : "=l"(a10) : "l"(w0),  "l"(x1.x), "l"(a10));
        asm("fma.rn.f32x2 %0, %1, %2, %3;" : "=l"(a11) : "l"(w1),  "l"(x1.x), "l"(a11));
        asm("fma.rn.f32x2 %0, %1, %2, %3;" : "=l"(a00) : "l"(w0b), "l"(x0.y), "l"(a00));
        asm("fma.rn.f32x2 %0, %1, %2, %3;" : "=l"(a01) : "l"(w1b), "l"(x0.y), "l"(a01));
        asm("fma.rn.f32x2 %0, %1, %2, %3;" : "=l"(a10) : "l"(w0b), "l"(x1.y), "l"(a10));
        asm("fma.rn.f32x2 %0, %1, %2, %3;" : "=l"(a11) : "l"(w1b), "l"(x1.y), "l"(a11));
    }
    rE[slot_e0]        = a00;
    rE[slot_e1]        = a01;
    rE[1024 + slot_e0] = a10;
    rE[1024 + slot_e1] = a11;
}

// ---------------- deferred combine + tanh + store (threads 256..511) ----------------
__device__ __forceinline__ void combine_store(int tid, int qc, const float* __restrict__ redEbuf,
                                              float bb, float* __restrict__ out) {
    int ct = tid - 256, pr = ct >> 7, dd = ct & 127;
    const float2* r = (const float2*)redEbuf + pr * 1024;
    float2 r0 = r[0 * 128 + dd];
    float2 r1 = r[1 * 128 + dd];
    float2 r2 = r[2 * 128 + dd];
    float2 r3 = r[3 * 128 + dd];
    float2 r4 = r[4 * 128 + dd];
    float2 r5 = r[5 * 128 + dd];
    float2 r6 = r[6 * 128 + dd];
    float2 r7 = r[7 * 128 + dd];
    float sx = ((r0.x + r1.x) + (r2.x + r3.x)) + ((r4.x + r5.x) + (r6.x + r7.x));
    float sy = ((r0.y + r1.y) + (r2.y + r3.y)) + ((r4.y + r5.y) + (r6.y + r7.y));
    float o0 = tanhf(sx + bb);
    float o1 = tanhf(sy + bb);
    size_t row = ((size_t)4 * qc + 2 * pr) * D;
    out[row + dd]     = o0;
    out[row + D + dd] = o1;
}

// ---------------- main fused kernel ----------------
__global__ void __launch_bounds__(T, 1)
gat_kernel(const float* __restrict__ h_ego, const float* __restrict__ h_nei,
           const int*   __restrict__ nbr_mask,
           const float* __restrict__ Wmsg, const float* __restrict__ Wself,
           const float* __restrict__ bself, float* __restrict__ out) {
    extern __shared__ float sm[];
    float* hn    = sm + OFF_HN;
    float* he    = sm + OFF_HE;
    int*   msk   = (int*)(sm + OFF_MSK);
    float* vs    = sm + OFF_VS;
    float* ego2  = sm + OFF_EGO2;
    float* agg2  = sm + OFF_AGG2;
    float* redD  = sm + OFF_REDD;
    float* redE  = sm + OFF_REDE;
    float* logit = sm + OFF_LOG;
    float* attn  = sm + OFF_ATT;

    const int tid  = threadIdx.x;
    const int lane = tid & 31;
    const int warp = tid >> 5;
    const int rr   = warp >> 2;           // row within quad (0..3)
    const int kq   = (warp & 3) * 8;      // 8 k's per warp

    // projection tile: m = matrix (0: Wmsg / agg2, 1: Wself / ego2)
    const int m    = tid >> 8;            // 0..1
    const int h    = (tid >> 6) & 3;      // input quarter
    const int e6   = tid & 63;            // output pair base (outputs e6 and e6+64)
    const int c0   = h * 32;              // first input dim
    const int slot_e0 = h * 256 + m * 128 + e6;
    const int slot_e1 = slot_e0 + 64;

    // W slices in registers: rows e6 and e6+64, cols [c0, c0+32)
    const float* Wsrc = (m == 0) ? Wmsg : Wself;
    float wreg[64];
    #pragma unroll
    for (int j = 0; j < 32; j += 4) {
        float4 t4 = *(const float4*)&Wsrc[e6 * D + c0 + j];
        wreg[j] = t4.x; wreg[j + 1] = t4.y; wreg[j + 2] = t4.z; wreg[j + 3] = t4.w;
        float4 t5 = *(const float4*)&Wsrc[(e6 + 64) * D + c0 + j];
        wreg[32 + j] = t5.x; wreg[33 + j] = t5.y; wreg[34 + j] = t5.z; wreg[35 + j] = t5.w;
    }
    if (tid < 2 * D) vs[tid] = g_v[tid];
    float bb = __ldg(bself + (tid & 127));
    __syncthreads();

    const uint32_t smem_u32 = (uint32_t)__cvta_generic_to_shared(sm);
    const float NEG_INF = __int_as_float(0xff800000);
    const int G = gridDim.x;

    int q = blockIdx.x;
    int s = 0;
    int it = 0;
    int lastq = -1;
    if (q < NQUAD) prefetch_quad(q, 0, tid, smem_u32, h_nei, h_ego, nbr_mask);
    cp_commit();

    for (; q < NQUAD; q += G, s ^= 1, it++) {
        int qn = q + G;
        if (qn < NQUAD) prefetch_quad(qn, s ^ 1, tid, smem_u32, h_nei, h_ego, nbr_mask);
        cp_commit();
        cp_wait1();
        __syncthreads();   // B0: buffer s ready; prev iteration's proj results visible

        const float* hnb  = &hn[s * 16384];
        const float* heb  = &he[s * 512];
        const int*   mskb = &msk[s * 128];
        const float* hb   = &hnb[rr * 4096 + kq * 128];

        // ---- stage fragments ONCE; compute raw neighbor dots ----
        float4 f0 = *(const float4*)&hb[0 * 128 + lane * 4];
        float4 f1 = *(const float4*)&hb[1 * 128 + lane * 4];
        float4 f2 = *(const float4*)&hb[2 * 128 + lane * 4];
        float4 f3 = *(const float4*)&hb[3 * 128 + lane * 4];
        float4 f4 = *(const float4*)&hb[4 * 128 + lane * 4];
        float4 f5 = *(const float4*)&hb[5 * 128 + lane * 4];
        float4 f6 = *(const float4*)&hb[6 * 128 + lane * 4];
        float4 f7 = *(const float4*)&hb[7 * 128 + lane * 4];
        {
            float4 vN = *(const float4*)&vs[D + lane * 4];
            float a0 = f0.x * vN.x + f0.y * vN.y + f0.z * vN.z + f0.w * vN.w;
            float a1 = f1.x * vN.x + f1.y * vN.y + f1.z * vN.z + f1.w * vN.w;
            float a2 = f2.x * vN.x + f2.y * vN.y + f2.z * vN.z + f2.w * vN.w;
            float a3 = f3.x * vN.x + f3.y * vN.y + f3.z * vN.z + f3.w * vN.w;
            float a4 = f4.x * vN.x + f4.y * vN.y + f4.z * vN.z + f4.w * vN.w;
            float a5 = f5.x * vN.x + f5.y * vN.y + f5.z * vN.z + f5.w * vN.w;
            float a6 = f6.x * vN.x + f6.y * vN.y + f6.z * vN.z + f6.w * vN.w;
            float a7 = f7.x * vN.x + f7.y * vN.y + f7.z * vN.z + f7.w * vN.w;

            // pair-combining butterfly: 8 values -> 1 per lane-class
            const unsigned FULL = 0xffffffffu;
            bool h16 = (lane & 16) != 0;
            float s0, o0;
            s0 = h16 ? a1 : a0; o0 = h16 ? a0 : a1;
            float b0 = s0 + __shfl_xor_sync(FULL, o0, 16);
            s0 = h16 ? a3 : a2; o0 = h16 ? a2 : a3;
            float b1 = s0 + __shfl_xor_sync(FULL, o0, 16);
            s0 = h16 ? a5 : a4; o0 = h16 ? a4 : a5;
            float b2 = s0 + __shfl_xor_sync(FULL, o0, 16);
            s0 = h16 ? a7 : a6; o0 = h16 ? a6 : a7;
            float b3 = s0 + __shfl_xor_sync(FULL, o0, 16);

            bool h8 = (lane & 8) != 0;
            s0 = h8 ? b1 : b0; o0 = h8 ? b0 : b1;
            float c0v = s0 + __shfl_xor_sync(FULL, o0, 8);
            s0 = h8 ? b3 : b2; o0 = h8 ? b2 : b3;
            float c1v = s0 + __shfl_xor_sync(FULL, o0, 8);

            bool h4 = (lane & 4) != 0;
            s0 = h4 ? c1v : c0v; o0 = h4 ? c0v : c1v;
            float dsum = s0 + __shfl_xor_sync(FULL, o0, 4);

            dsum += __shfl_xor_sync(FULL, dsum, 2);
            dsum += __shfl_xor_sync(FULL, dsum, 1);

            if ((lane & 3) == 0) {
                int kl = ((lane >> 4) & 1) | (((lane >> 3) & 1) << 1) | (((lane >> 2) & 1) << 2);
                logit[rr * KNBR + kq + kl] = dsum;
            }
        }
        // pack ego batch-major (threads 256..511 handle 2 each) — needed before A1
        if (tid >= 256) {
            int t = tid - 256;
            #pragma unroll
            for (int i = 0; i < 2; i++) {
                int idx = t + i * 256;          // 0..511
                int r = idx >> 7, dd = idx & 127;
                ego2[(r >> 1) * 256 + 2 * dd + (r & 1)] = heb[r * 128 + dd];
            }
        }
        __syncthreads();   // A1: logits + ego2 ready

        // ---- softmax (warps 0..3) || ego projection (warps 8..15, m=1) ----
        if (warp < 4) {
            float4 vE = *(const float4*)&vs[lane * 4];
            float4 eg = *(const float4*)&heb[warp * 128 + lane * 4];
            float pe = eg.x * vE.x + eg.y * vE.y + eg.z * vE.z + eg.w * vE.w;
            #pragma unroll
            for (int o = 16; o > 0; o >>= 1) pe += __shfl_xor_sync(0xffffffffu, pe, o);
            float x = logit[warp * KNBR + lane] + pe;
            x = (x > 0.f) ? x : 0.2f * x;                          // leaky_relu
            x = (mskb[warp * KNBR + lane] > 0) ? x : NEG_INF;      // mask
            float mx = x;
            #pragma unroll
            for (int o = 16; o > 0; o >>= 1) mx = fmaxf(mx, __shfl_xor_sync(0xffffffffu, mx, o));
            float ee = (x == NEG_INF) ? 0.f : __expf(x - mx);
            float ss = ee;
            #pragma unroll
            for (int o = 16; o > 0; o >>= 1) ss += __shfl_xor_sync(0xffffffffu, ss, o);
            attn[warp * KNBR + lane] = (ss > 0.f) ? (ee / ss) : 0.f;
        } else if (tid >= 256) {
            // ego @ Wself^T for both pairs — independent of attention
            proj2x32((const unsigned long long*)ego2, wreg, c0,
                     (unsigned long long*)(redE + s * 4096), slot_e0, slot_e1);
        }
        __syncthreads();   // A2: attn ready

        // ---- weighted partial aggregation from HELD registers ----
        {
            float4 atv0 = *(const float4*)&attn[rr * KNBR + kq];
            float4 atv1 = *(const float4*)&attn[rr * KNBR + kq + 4];
            float a0 = atv0.x, a1 = atv0.y, a2 = atv0.z, a3 = atv0.w;
            float a4 = atv1.x, a5 = atv1.y, a6 = atv1.z, a7 = atv1.w;
            float4 acc;
            acc.x = a0 * f0.x; acc.y = a0 * f0.y; acc.z = a0 * f0.z; acc.w = a0 * f0.w;
            acc.x = fmaf(a1, f1.x, acc.x); acc.y = fmaf(a1, f1.y, acc.y);
            acc.z = fmaf(a1, f1.z, acc.z); acc.w = fmaf(a1, f1.w, acc.w);
            acc.x = fmaf(a2, f2.x, acc.x); acc.y = fmaf(a2, f2.y, acc.y);
            acc.z = fmaf(a2, f2.z, acc.z); acc.w = fmaf(a2, f2.w, acc.w);
            acc.x = fmaf(a3, f3.x, acc.x); acc.y = fmaf(a3, f3.y, acc.y);
            acc.z = fmaf(a3, f3.z, acc.z); acc.w = fmaf(a3, f3.w, acc.w);
            acc.x = fmaf(a4, f4.x, acc.x); acc.y = fmaf(a4, f4.y, acc.y);
            acc.z = fmaf(a4, f4.z, acc.z); acc.w = fmaf(a4, f4.w, acc.w);
            acc.x = fmaf(a5, f5.x, acc.x); acc.y = fmaf(a5, f5.y, acc.y);
            acc.z = fmaf(a5, f5.z, acc.z); acc.w = fmaf(a5, f5.w, acc.w);
            acc.x = fmaf(a6, f6.x, acc.x); acc.y = fmaf(a6, f6.y, acc.y);
            acc.z = fmaf(a6, f6.z, acc.z); acc.w = fmaf(a6, f6.w, acc.w);
            acc.x = fmaf(a7, f7.x, acc.x); acc.y = fmaf(a7, f7.y, acc.y);
            acc.z = fmaf(a7, f7.z, acc.z); acc.w = fmaf(a7, f7.w, acc.w);
            ((float4*)redD)[warp * 32 + lane] = acc;
        }
        __syncthreads();   // A3

        // ---- reduce 4 partials per (row,dim) -> batch-packed agg2 ----
        {
            int r  = tid >> 7;        // 0..3 (row)
            int dd = tid & 127;
            const float* rb = &redD[(4 * r) * 128 + dd];
            agg2[(r >> 1) * 256 + 2 * dd + (r & 1)] =
                rb[0] + rb[128] + rb[256] + rb[384];
        }
        __syncthreads();   // A4

        // ---- msg proj (threads 0..255, fma) || deferred combine of PREV quad
        //      (threads 256..511: LDS/MUFU/STG — pipe-mixed window) ----
        if (tid < 256) {
            proj2x32((const unsigned long long*)agg2, wreg, c0,
                     (unsigned long long*)(redE + s * 4096), slot_e0, slot_e1);
        } else if (it > 0) {
            combine_store(tid, q - G, redE + (s ^ 1) * 4096, bb, out);
        }
        lastq = q;
        // no A5: redE[s] consumed next iteration after B0 (or in epilogue)
    }
    cp_waitall();
    __syncthreads();   // final proj results visible
    if (lastq >= 0 && tid >= 256)
        combine_store(tid, lastq, redE + (s ^ 1) * 4096, bb, out);
}

// ---------------- launch ----------------
extern "C" void kernel_launch(void* const* d_in, const int* in_sizes, int n_in,
                              void* d_out, int out_size) {
    const float* h_ego  = (const float*)d_in[0];
    const float* h_nei  = (const float*)d_in[1];
    const int*   nmask  = (const int*)  d_in[2];
    const float* Wmsg   = (const float*)d_in[3];
    const float* Wattn  = (const float*)d_in[4];
    const float* Wself  = (const float*)d_in[5];
    const float* bself  = (const float*)d_in[6];
    float* out = (float*)d_out;

    int sms = 0;
    cudaDeviceGetAttribute(&sms, cudaDevAttrMultiProcessorCount, 0);
    if (sms <= 0) sms = 148;

    cudaFuncSetAttribute(gat_kernel, cudaFuncAttributeMaxDynamicSharedMemorySize, SMEM_BYTES);

    prep_kernel<<<1, D>>>(Wmsg, Wattn);
    gat_kernel<<<sms, T, SMEM_BYTES>>>(h_ego, h_nei, nmask, Wmsg, Wself, bself, out);
}